// round 1
// baseline (speedup 1.0000x reference)
#include <cuda_runtime.h>
#include <cstdint>

// VectorQuantizer: z[32,64,32,32] fp32, codebook[1024,64] fp32
// out = [ z_q (2097152 f32) | loss (1 f32) | indices (32768 f32) ]

#define N_PIX    32768
#define C_DIM    64
#define K_CB     1024
#define P_BLK    64
#define K_TILE   128
#define NTHREADS 256
#define Z_ELEMS  2097152

// scratch (no cudaMalloc allowed)
__device__ float  g_Et[C_DIM * K_CB];   // transposed codebook [c][k]
__device__ float  g_e2[K_CB];           // sum(e^2) per code
__device__ double g_sum;                // loss accumulator

__device__ __forceinline__ unsigned long long pack2dup(float x) {
    unsigned long long r;
    unsigned int u = __float_as_uint(x);
    asm("mov.b64 %0, {%1, %1};" : "=l"(r) : "r"(u));
    return r;
}
__device__ __forceinline__ void fma2(unsigned long long& d,
                                     unsigned long long a,
                                     unsigned long long b) {
    asm("fma.rn.f32x2 %0, %1, %2, %0;" : "+l"(d) : "l"(a), "l"(b));
}
__device__ __forceinline__ float2 unpack2(unsigned long long v) {
    unsigned int a, b;
    asm("mov.b64 {%0, %1}, %2;" : "=r"(a), "=r"(b) : "l"(v));
    return make_float2(__uint_as_float(a), __uint_as_float(b));
}

// ---------------------------------------------------------------------------
// Prep: transpose codebook -> g_Et[c][k], compute g_e2[k], zero loss accum.
// ---------------------------------------------------------------------------
__global__ void vq_prep(const float* __restrict__ cb) {
    int k = blockIdx.x * blockDim.x + threadIdx.x;
    if (k == 0) g_sum = 0.0;
    if (k < K_CB) {
        float s = 0.f;
        #pragma unroll
        for (int c = 0; c < C_DIM; c++) {
            float v = cb[k * C_DIM + c];
            g_Et[c * K_CB + k] = v;
            s = __fadd_rn(s, __fmul_rn(v, v));
        }
        g_e2[k] = s;
    }
}

// ---------------------------------------------------------------------------
// Main: per block 64 pixels; loop 8 tiles of 128 codes in smem.
// Thread (tx,ty): tx=tid&15 (code group of 8), ty=tid>>4 (pixel group of 4).
// d_k = (sum_z2 + e2_k) - 2*dot  (replicates reference expression tree).
// ---------------------------------------------------------------------------
__global__ __launch_bounds__(NTHREADS)
void vq_main(const float* __restrict__ z, float* __restrict__ out) {
    extern __shared__ float smem[];
    float*  sZ   = smem;                     // [64][64]  16KB
    float*  sE   = smem + 4096;              // [64][128] 32KB
    float*  sE2  = sE + 8192;                // [128]
    int*    sIdx = (int*)(sE2 + 128);        // [64]
    double* sRed = (double*)(sIdx + 64);     // [8]

    const int tid = threadIdx.x;
    const int tx  = tid & 15;
    const int ty  = tid >> 4;
    const int n0  = blockIdx.x * P_BLK;
    const int b   = n0 >> 10;
    const int p0  = n0 & 1023;
    const float* zb = z + (size_t)b * 65536 + p0;   // + c*1024 + px

    // load z tile [c][px], coalesced over px
    for (int i = tid; i < P_BLK * C_DIM; i += NTHREADS) {
        int c = i >> 6, px = i & 63;
        sZ[c * 64 + px] = zb[c * 1024 + px];
    }
    __syncthreads();

    // sum(z^2) for my 4 pixels (sequential fp32, same binade => shared-offset safe)
    float sz[4];
    #pragma unroll
    for (int p = 0; p < 4; p++) {
        int px = ty * 4 + p;
        float s = 0.f;
        #pragma unroll
        for (int c = 0; c < C_DIM; c++) {
            float v = sZ[c * 64 + px];
            s = __fadd_rn(s, __fmul_rn(v, v));
        }
        sz[p] = s;
    }

    float best[4]; int bidx[4];
    #pragma unroll
    for (int p = 0; p < 4; p++) { best[p] = 3.4e38f; bidx[p] = 0; }

    for (int t = 0; t < K_CB / K_TILE; t++) {
        __syncthreads();   // protect previous tile's readers
        for (int i = tid; i < C_DIM * K_TILE; i += NTHREADS) {
            int c = i >> 7, k = i & 127;
            sE[c * 128 + k] = g_Et[c * 1024 + t * 128 + k];
        }
        if (tid < 128) sE2[tid] = g_e2[t * 128 + tid];
        __syncthreads();

        unsigned long long acc[4][4];
        #pragma unroll
        for (int p = 0; p < 4; p++)
            #pragma unroll
            for (int q = 0; q < 4; q++) acc[p][q] = 0ull;

        const float* zrow = sZ + ty * 4;
        const float* erow = sE + tx * 8;

        #pragma unroll 16
        for (int c = 0; c < C_DIM; c++) {
            float4  zv = *(const float4*)(zrow + c * 64);
            double2 ea = *(const double2*)(erow + c * 128);
            double2 eb = *(const double2*)(erow + c * 128 + 4);
            unsigned long long e01 = __double_as_longlong(ea.x);
            unsigned long long e23 = __double_as_longlong(ea.y);
            unsigned long long e45 = __double_as_longlong(eb.x);
            unsigned long long e67 = __double_as_longlong(eb.y);
            unsigned long long zz[4];
            zz[0] = pack2dup(zv.x); zz[1] = pack2dup(zv.y);
            zz[2] = pack2dup(zv.z); zz[3] = pack2dup(zv.w);
            #pragma unroll
            for (int p = 0; p < 4; p++) {
                fma2(acc[p][0], zz[p], e01);
                fma2(acc[p][1], zz[p], e23);
                fma2(acc[p][2], zz[p], e45);
                fma2(acc[p][3], zz[p], e67);
            }
        }

        // d = (sz + e2) - 2*dot ; strict < with ascending k = first-index ties
        #pragma unroll
        for (int p = 0; p < 4; p++) {
            #pragma unroll
            for (int q = 0; q < 4; q++) {
                float2 dp = unpack2(acc[p][q]);
                int kl = tx * 8 + q * 2;
                float base0 = __fadd_rn(sz[p], sE2[kl]);
                float base1 = __fadd_rn(sz[p], sE2[kl + 1]);
                float d0 = __fadd_rn(base0, __fmul_rn(-2.f, dp.x));
                float d1 = __fadd_rn(base1, __fmul_rn(-2.f, dp.y));
                int kg = t * 128 + kl;
                if (d0 < best[p]) { best[p] = d0; bidx[p] = kg; }
                if (d1 < best[p]) { best[p] = d1; bidx[p] = kg + 1; }
            }
        }
    }

    // reduce argmin across the 16 code-group lanes (consecutive lanes)
    #pragma unroll
    for (int p = 0; p < 4; p++) {
        float bv = best[p]; int bi = bidx[p];
        #pragma unroll
        for (int off = 8; off >= 1; off >>= 1) {
            float ov = __shfl_xor_sync(0xffffffffu, bv, off);
            int   oi = __shfl_xor_sync(0xffffffffu, bi, off);
            if (ov < bv || (ov == bv && oi < bi)) { bv = ov; bi = oi; }
        }
        if (tx == 0) sIdx[ty * 4 + p] = bi;
    }
    __syncthreads();

    // epilogue: z_q = z + (e - z) (straight-through), loss partials, indices
    double lsum = 0.0;
    for (int i = tid; i < P_BLK * C_DIM; i += NTHREADS) {
        int c = i >> 6, px = i & 63;
        int k = sIdx[px];
        float ev  = g_Et[c * 1024 + k];
        float zv  = sZ[c * 64 + px];
        float tdf = __fadd_rn(ev, -zv);
        out[(size_t)b * 65536 + c * 1024 + p0 + px] = __fadd_rn(zv, tdf);
        lsum += (double)__fmul_rn(tdf, tdf);
    }
    if (tid < P_BLK)
        out[(size_t)Z_ELEMS + 1 + n0 + tid] = (float)sIdx[tid];

    // block-reduce loss
    #pragma unroll
    for (int off = 16; off >= 1; off >>= 1)
        lsum += __shfl_down_sync(0xffffffffu, lsum, off);
    if ((tid & 31) == 0) sRed[tid >> 5] = lsum;
    __syncthreads();
    if (tid == 0) {
        double s = 0.0;
        #pragma unroll
        for (int w = 0; w < 8; w++) s += sRed[w];
        atomicAdd(&g_sum, s);
    }
}

// ---------------------------------------------------------------------------
__global__ void vq_finish(float* __restrict__ out) {
    double m = g_sum / (double)Z_ELEMS;
    float mf = (float)m;                       // q_latent == e_latent numerically
    out[Z_ELEMS] = __fadd_rn(mf, __fmul_rn(0.25f, mf));
}

extern "C" void kernel_launch(void* const* d_in, const int* in_sizes, int n_in,
                              void* d_out, int out_size) {
    const float* z  = (const float*)d_in[0];
    const float* cb = (const float*)d_in[1];
    float* out = (float*)d_out;

    const int smem_bytes = (4096 + 8192 + 128) * 4 + 64 * 4 + 8 * 8;  // 49984
    cudaFuncSetAttribute(vq_main, cudaFuncAttributeMaxDynamicSharedMemorySize,
                         smem_bytes);

    vq_prep<<<4, 256>>>(cb);
    vq_main<<<N_PIX / P_BLK, NTHREADS, smem_bytes>>>(z, out);
    vq_finish<<<1, 1>>>(out);
}

// round 2
// speedup vs baseline: 1.4735x; 1.4735x over previous
#include <cuda_runtime.h>
#include <cstdint>

// VectorQuantizer: z[32,64,32,32] fp32, codebook[1024,64] fp32
// out = [ z_q (2097152 f32) | loss (1 f32) | indices (32768 f32) ]

#define C_DIM    64
#define K_CB     1024
#define P_BLK    32
#define K_TILE   128
#define NT       128
#define Z_ELEMS  2097152
#define N_PIX    32768
#define GRID_MAIN (N_PIX / P_BLK)   // 1024

// device scratch (no cudaMalloc allowed)
__device__ float    g_Et[C_DIM * K_CB];   // transposed codebook [c][k]
__device__ float    g_e2[K_CB];           // sum(e^2) per code (sequential-c order)
__device__ float    g_z2[N_PIX];          // sum(z^2) per pixel (sequential-c order)
__device__ double   g_sum;                // loss accumulator
__device__ unsigned g_ticket;             // last-block detector

__device__ __forceinline__ unsigned long long pack2dup(float x) {
    unsigned long long r;
    unsigned int u = __float_as_uint(x);
    asm("mov.b64 %0, {%1, %1};" : "=l"(r) : "r"(u));
    return r;
}
__device__ __forceinline__ void fma2(unsigned long long& d,
                                     unsigned long long a,
                                     unsigned long long b) {
    asm("fma.rn.f32x2 %0, %1, %2, %0;" : "+l"(d) : "l"(a), "l"(b));
}
__device__ __forceinline__ float2 unpack2(unsigned long long v) {
    unsigned int a, b;
    asm("mov.b64 {%0, %1}, %2;" : "=r"(a), "=r"(b) : "l"(v));
    return make_float2(__uint_as_float(a), __uint_as_float(b));
}

// ---------------------------------------------------------------------------
// Prep (192 blocks x 256): transpose codebook, e2 (seq c), z2 (seq c), resets.
// ---------------------------------------------------------------------------
__global__ void vq_prep(const float* __restrict__ cb, const float* __restrict__ z) {
    int id = blockIdx.x * blockDim.x + threadIdx.x;
    if (id == 0) { g_sum = 0.0; g_ticket = 0u; }

    if (id < 16384) {            // transpose: id = k*16 + c4chunk
        int k  = id >> 4;
        int c4 = (id & 15) * 4;
        float4 v = *(const float4*)(cb + k * 64 + c4);
        g_Et[(c4 + 0) * 1024 + k] = v.x;
        g_Et[(c4 + 1) * 1024 + k] = v.y;
        g_Et[(c4 + 2) * 1024 + k] = v.z;
        g_Et[(c4 + 3) * 1024 + k] = v.w;
    }
    if (id < 1024) {             // e2: strict sequential over c
        const float* row = cb + id * 64;
        float s = 0.f;
        #pragma unroll
        for (int c = 0; c < 64; c++)
            s = __fadd_rn(s, __fmul_rn(row[c], row[c]));
        g_e2[id] = s;
    }
    if (id >= 16384 && id < 16384 + N_PIX) {   // z2: strict sequential over c
        int n = id - 16384;
        int b = n >> 10, p = n & 1023;
        const float* zp = z + (size_t)b * 65536 + p;
        float s = 0.f;
        #pragma unroll
        for (int c = 0; c < 64; c++) {
            float v = zp[c * 1024];
            s = __fadd_rn(s, __fmul_rn(v, v));
        }
        g_z2[n] = s;
    }
}

// ---------------------------------------------------------------------------
// Main: block = 32 pixels. 8 tiles of 128 codes.
// Thread (tx=tid&15 -> 8 codes as 4 f32x2 pairs, ty=tid>>4 -> 4 pixels).
// z pre-duplicated in smem as (v,v) f32x2 -> inner loop has NO MOVs.
// Codes packed in f32x2 lanes; each dot is one sequential chain over c=0..63.
// d = fl( fl(sz+e2) - 2*dot )   (2*dot exact, so fused FFMA == reference tree)
// ---------------------------------------------------------------------------
__global__ __launch_bounds__(NT, 4)
void vq_main(const float* __restrict__ z, float* __restrict__ out) {
    extern __shared__ char smem_raw[];
    unsigned long long* sZd = (unsigned long long*)smem_raw;     // [64][32] dup pairs, 16KB
    float*  sE   = (float*)(sZd + 64 * 32);                      // [64][128] 32KB
    float*  sE2  = sE + 64 * 128;                                // [128]
    int*    sIdx = (int*)(sE2 + 128);                            // [32]
    double* sRed = (double*)(sIdx + 32);                         // [4]

    const int tid = threadIdx.x;
    const int tx  = tid & 15;
    const int ty  = tid >> 4;
    const int pxb = ty * 4;
    const int n0  = blockIdx.x * P_BLK;
    const int b   = n0 >> 10;
    const int p0  = n0 & 1023;
    const float* zb = z + (size_t)b * 65536 + p0;

    // load z tile, duplicating each value into an f32x2 pair
    for (int i = tid; i < 64 * 32; i += NT) {
        int c = i >> 5, px = i & 31;
        sZd[c * 32 + px] = pack2dup(zb[c * 1024 + px]);
    }

    float sz[4];
    #pragma unroll
    for (int p = 0; p < 4; p++) sz[p] = g_z2[n0 + pxb + p];

    float best[4]; int bidx[4];
    #pragma unroll
    for (int p = 0; p < 4; p++) { best[p] = 3.4e38f; bidx[p] = 0; }

    for (int t = 0; t < K_CB / K_TILE; t++) {
        __syncthreads();
        // load E tile [64][128] (coalesced 512B per warp, conflict-free STS)
        for (int i = tid; i < 2048; i += NT) {
            int c = i >> 5, kk = (i & 31) * 4;
            *(float4*)(sE + c * 128 + kk) =
                *(const float4*)(g_Et + c * 1024 + t * 128 + kk);
        }
        sE2[tid] = g_e2[t * 128 + tid];
        __syncthreads();

        unsigned long long acc[4][4];
        #pragma unroll
        for (int p = 0; p < 4; p++)
            #pragma unroll
            for (int q = 0; q < 4; q++) acc[p][q] = 0ull;

        #pragma unroll 8
        for (int c = 0; c < C_DIM; c++) {
            // 4 pixels (dup pairs): two LDS.128, broadcast across tx lanes
            ulonglong2 za = *(const ulonglong2*)(sZd + c * 32 + pxb);
            ulonglong2 zc = *(const ulonglong2*)(sZd + c * 32 + pxb + 2);
            // 8 codes as 4 natural f32x2 pairs: two LDS.128, conflict-free
            ulonglong2 ea = *(const ulonglong2*)(sE + c * 128 + 4 * tx);
            ulonglong2 eb = *(const ulonglong2*)(sE + c * 128 + 64 + 4 * tx);
            unsigned long long zp[4] = { za.x, za.y, zc.x, zc.y };
            #pragma unroll
            for (int p = 0; p < 4; p++) {
                fma2(acc[p][0], zp[p], ea.x);
                fma2(acc[p][1], zp[p], ea.y);
                fma2(acc[p][2], zp[p], eb.x);
                fma2(acc[p][3], zp[p], eb.y);
            }
        }

        // d = fl(sz+e2) - 2*dot; strict < keeps first (smallest) index per thread
        #pragma unroll
        for (int q = 0; q < 4; q++) {
            int k0 = (q < 2) ? (4 * tx + 2 * q) : (64 + 4 * tx + 2 * (q - 2));
            float e20 = sE2[k0], e21 = sE2[k0 + 1];
            int kg = t * 128 + k0;
            #pragma unroll
            for (int p = 0; p < 4; p++) {
                float2 dp = unpack2(acc[p][q]);
                float d0 = __fmaf_rn(dp.x, -2.f, __fadd_rn(sz[p], e20));
                float d1 = __fmaf_rn(dp.y, -2.f, __fadd_rn(sz[p], e21));
                if (d0 < best[p]) { best[p] = d0; bidx[p] = kg; }
                if (d1 < best[p]) { best[p] = d1; bidx[p] = kg + 1; }
            }
        }
    }

    // argmin reduce across the 16 tx lanes (xor widths stay inside 16-lane halves)
    #pragma unroll
    for (int p = 0; p < 4; p++) {
        float bv = best[p]; int bi = bidx[p];
        #pragma unroll
        for (int off = 8; off >= 1; off >>= 1) {
            float ov = __shfl_xor_sync(0xffffffffu, bv, off);
            int   oi = __shfl_xor_sync(0xffffffffu, bi, off);
            if (ov < bv || (ov == bv && oi < bi)) { bv = ov; bi = oi; }
        }
        if (tx == 0) sIdx[pxb + p] = bi;
    }
    __syncthreads();

    // epilogue: gather, straight-through output, loss partial, indices
    double lsum = 0.0;
    for (int i = tid; i < P_BLK * C_DIM; i += NT) {
        int c = i >> 5, px = i & 31;
        int k = sIdx[px];
        float ev  = g_Et[c * 1024 + k];
        float zv  = __uint_as_float((unsigned)(sZd[c * 32 + px] & 0xffffffffu));
        float tdf = __fadd_rn(ev, -zv);
        out[(size_t)b * 65536 + c * 1024 + p0 + px] = __fadd_rn(zv, tdf);
        lsum += (double)__fmul_rn(tdf, tdf);
    }
    if (tid < P_BLK)
        out[(size_t)Z_ELEMS + 1 + n0 + tid] = (float)sIdx[tid];

    #pragma unroll
    for (int off = 16; off >= 1; off >>= 1)
        lsum += __shfl_down_sync(0xffffffffu, lsum, off);
    if ((tid & 31) == 0) sRed[tid >> 5] = lsum;
    __syncthreads();

    // fused finish: last block writes the loss
    if (tid == 0) {
        double s = sRed[0] + sRed[1] + sRed[2] + sRed[3];
        atomicAdd(&g_sum, s);
        __threadfence();
        unsigned tk = atomicAdd(&g_ticket, 1u);
        if (tk == (unsigned)(gridDim.x - 1)) {
            double tot = atomicAdd(&g_sum, 0.0);   // returns final sum
            float mf = (float)(tot / (double)Z_ELEMS);
            out[Z_ELEMS] = __fadd_rn(mf, __fmul_rn(0.25f, mf));
        }
    }
}

extern "C" void kernel_launch(void* const* d_in, const int* in_sizes, int n_in,
                              void* d_out, int out_size) {
    const float* z  = (const float*)d_in[0];
    const float* cb = (const float*)d_in[1];
    float* out = (float*)d_out;

    const int smem_bytes = 64 * 32 * 8 + 64 * 128 * 4 + 128 * 4 + 32 * 4 + 4 * 8;
    cudaFuncSetAttribute(vq_main, cudaFuncAttributeMaxDynamicSharedMemorySize,
                         smem_bytes);

    vq_prep<<<192, 256>>>(cb, z);
    vq_main<<<GRID_MAIN, NT, smem_bytes>>>(z, out);
}